// round 7
// baseline (speedup 1.0000x reference)
#include <cuda_runtime.h>

// WaveletLayer fused: db2 DWT -> scale -> inverse DWT -> ReLU, fully collapsed.
//
// QMF identity (hi[i] = (-1)^i lo[3-i]) collapses the chain to, per input
// pair (u,v) = (x[2m], x[2m+1]), with t = sqrt(3)/4:
//   p = 0.75u - t*v,  q = u - p
//   r = 0.25v - t*u,  s = v - r
//   out[2m]   = relu(k[m]*p + k[m+1]*q)
//   out[2m+1] = relu(k[m]*r + k[m+1]*s)
// Boundary/padding contributions cancel identically.
//
// R7: persistent CTAs (1184 = 8/SM) looping over 8192 tiles with a register
// double-buffer: next tile's 4 LDG.128 are issued before computing the
// current tile, so loads stay continuously in flight across tile boundaries
// and wave-transition bubbles disappear. Tile = half-row (2048 cols), same
// per-thread shape as the best R5 kernel.

#define NCOL  4096
#define LOUT  2049
#define NT    256
#define TILES 8192
#define GRID  1184   // 8 blocks per SM x 148 SMs

__device__ __forceinline__ void wave_compute_store(
    float4 X0, float4 X1, float4 F0, float4 F1, int d,
    float* __restrict__ outp)
{
    // uniform 4-way select of K window K[m0..m0+4]
    float k0, k1, k2, k3, k4;
    if (d == 0)      { k0 = F0.x; k1 = F0.y; k2 = F0.z; k3 = F0.w; k4 = F1.x; }
    else if (d == 1) { k0 = F0.y; k1 = F0.z; k2 = F0.w; k3 = F1.x; k4 = F1.y; }
    else if (d == 2) { k0 = F0.z; k1 = F0.w; k2 = F1.x; k3 = F1.y; k4 = F1.z; }
    else             { k0 = F0.w; k1 = F1.x; k2 = F1.y; k3 = F1.z; k4 = F1.w; }

    const float T = 0.43301270189221932f;  // sqrt(3)/4
    float u, v, p, q, rr, ss;
    float4 r0, r1;

    u = X0.x; v = X0.y;
    p = fmaf(-T, v, 0.75f * u); q = u - p;
    rr = fmaf(-T, u, 0.25f * v); ss = v - rr;
    r0.x = fmaxf(fmaf(k1, q,  k0 * p),  0.0f);
    r0.y = fmaxf(fmaf(k1, ss, k0 * rr), 0.0f);

    u = X0.z; v = X0.w;
    p = fmaf(-T, v, 0.75f * u); q = u - p;
    rr = fmaf(-T, u, 0.25f * v); ss = v - rr;
    r0.z = fmaxf(fmaf(k2, q,  k1 * p),  0.0f);
    r0.w = fmaxf(fmaf(k2, ss, k1 * rr), 0.0f);

    u = X1.x; v = X1.y;
    p = fmaf(-T, v, 0.75f * u); q = u - p;
    rr = fmaf(-T, u, 0.25f * v); ss = v - rr;
    r1.x = fmaxf(fmaf(k3, q,  k2 * p),  0.0f);
    r1.y = fmaxf(fmaf(k3, ss, k2 * rr), 0.0f);

    u = X1.z; v = X1.w;
    p = fmaf(-T, v, 0.75f * u); q = u - p;
    rr = fmaf(-T, u, 0.25f * v); ss = v - rr;
    r1.z = fmaxf(fmaf(k4, q,  k3 * p),  0.0f);
    r1.w = fmaxf(fmaf(k4, ss, k3 * rr), 0.0f);

    float4* o4 = reinterpret_cast<float4*>(outp);
    __stcs(o4,     r0);
    __stcs(o4 + 1, r1);
}

__global__ __launch_bounds__(NT) void wavelet_fused_kernel(
    const float* __restrict__ x,
    const float* __restrict__ kern,
    float* __restrict__ out)
{
    const int tid = threadIdx.x;

    int t = blockIdx.x;

    // ---- prologue: load current tile ----
    int   row = t >> 1;
    int   m0  = ((t & 1) * NT + tid) * 4;
    size_t off = (size_t)row * NCOL + 2 * m0;
    int   w   = LOUT * row + m0;
    int   d   = w & 3;

    float4 X0 = *reinterpret_cast<const float4*>(x + off);
    float4 X1 = *reinterpret_cast<const float4*>(x + off + 4);
    float4 F0 = *reinterpret_cast<const float4*>(kern + (w - d));
    float4 F1 = *reinterpret_cast<const float4*>(kern + (w - d) + 4);

    while (true) {
        const int tn = t + GRID;          // uniform across block
        if (tn < TILES) {
            // ---- issue next tile's loads before computing current ----
            int   nrow = tn >> 1;
            int   nm0  = ((tn & 1) * NT + tid) * 4;
            size_t noff = (size_t)nrow * NCOL + 2 * nm0;
            int   nw   = LOUT * nrow + nm0;
            int   nd   = nw & 3;

            float4 nX0 = *reinterpret_cast<const float4*>(x + noff);
            float4 nX1 = *reinterpret_cast<const float4*>(x + noff + 4);
            float4 nF0 = *reinterpret_cast<const float4*>(kern + (nw - nd));
            float4 nF1 = *reinterpret_cast<const float4*>(kern + (nw - nd) + 4);

            wave_compute_store(X0, X1, F0, F1, d, out + off);

            X0 = nX0; X1 = nX1; F0 = nF0; F1 = nF1;
            off = noff; d = nd; t = tn;
        } else {
            wave_compute_store(X0, X1, F0, F1, d, out + off);
            break;
        }
    }
}

extern "C" void kernel_launch(void* const* d_in, const int* in_sizes, int n_in,
                              void* d_out, int out_size)
{
    const float* x    = (const float*)d_in[0];
    const float* kern = (const float*)d_in[1];
    float*       out  = (float*)d_out;

    wavelet_fused_kernel<<<GRID, NT>>>(x, kern, out);
}

// round 8
// speedup vs baseline: 1.3017x; 1.3017x over previous
#include <cuda_runtime.h>

// WaveletLayer fused: db2 DWT -> scale -> inverse DWT -> ReLU, fully collapsed.
//
// QMF identity (hi[i] = (-1)^i lo[3-i]) collapses the chain to, per input
// pair (u,v) = (x[2m], x[2m+1]), with t = sqrt(3)/4:
//   p = 0.75u - t*v,  q = u - p
//   r = 0.25v - t*u,  s = v - r
//   out[2m]   = relu(k[m]*p + k[m+1]*q)
//   out[2m+1] = relu(k[m]*r + k[m+1]*s)
// Boundary/padding contributions cancel identically.
//
// R8: R5 per-thread shape (<=32 regs -> full occupancy on the 64K-reg SM),
// one 512-thread block per row (less block overhead, no row split),
// __ldcs streaming loads for x (protect K's L2 residency), .cs stores.

#define NCOL 4096
#define LOUT 2049
#define NT   512

__global__ __launch_bounds__(NT) void wavelet_fused_kernel(
    const float* __restrict__ x,
    const float* __restrict__ kern,
    float* __restrict__ out)
{
    const int row  = blockIdx.x;
    const int m0   = threadIdx.x * 4;     // first pair index (0..2044)
    const int base = 2 * m0;              // first output column

    // x[base .. base+7]: two aligned streaming float4 loads
    const float4* x4 = reinterpret_cast<const float4*>(x + (size_t)row * NCOL + base);
    float4 X0 = __ldcs(x4);
    float4 X1 = __ldcs(x4 + 1);

    // K window K[m0..m0+4]: block-uniform misalignment d = row & 3,
    // covered by 2 aligned float4 loads + uniform select.
    // (Tail-safe: last row has d=3, read ends exactly at kern's last element.)
    const int w = LOUT * row + m0;
    const int d = w & 3;
    const float4* kp = reinterpret_cast<const float4*>(kern + (w - d));
    float4 F0 = kp[0];
    float4 F1 = kp[1];
    float k0, k1, k2, k3, k4;
    if (d == 0)      { k0 = F0.x; k1 = F0.y; k2 = F0.z; k3 = F0.w; k4 = F1.x; }
    else if (d == 1) { k0 = F0.y; k1 = F0.z; k2 = F0.w; k3 = F1.x; k4 = F1.y; }
    else if (d == 2) { k0 = F0.z; k1 = F0.w; k2 = F1.x; k3 = F1.y; k4 = F1.z; }
    else             { k0 = F0.w; k1 = F1.x; k2 = F1.y; k3 = F1.z; k4 = F1.w; }

    const float T = 0.43301270189221932f;  // sqrt(3)/4

    float u, v, p, q, rr, ss;
    float4 r0, r1;

    u = X0.x; v = X0.y;
    p = fmaf(-T, v, 0.75f * u); q = u - p;
    rr = fmaf(-T, u, 0.25f * v); ss = v - rr;
    r0.x = fmaxf(fmaf(k1, q,  k0 * p),  0.0f);
    r0.y = fmaxf(fmaf(k1, ss, k0 * rr), 0.0f);

    u = X0.z; v = X0.w;
    p = fmaf(-T, v, 0.75f * u); q = u - p;
    rr = fmaf(-T, u, 0.25f * v); ss = v - rr;
    r0.z = fmaxf(fmaf(k2, q,  k1 * p),  0.0f);
    r0.w = fmaxf(fmaf(k2, ss, k1 * rr), 0.0f);

    u = X1.x; v = X1.y;
    p = fmaf(-T, v, 0.75f * u); q = u - p;
    rr = fmaf(-T, u, 0.25f * v); ss = v - rr;
    r1.x = fmaxf(fmaf(k3, q,  k2 * p),  0.0f);
    r1.y = fmaxf(fmaf(k3, ss, k2 * rr), 0.0f);

    u = X1.z; v = X1.w;
    p = fmaf(-T, v, 0.75f * u); q = u - p;
    rr = fmaf(-T, u, 0.25f * v); ss = v - rr;
    r1.z = fmaxf(fmaf(k4, q,  k3 * p),  0.0f);
    r1.w = fmaxf(fmaf(k4, ss, k3 * rr), 0.0f);

    float4* o4 = reinterpret_cast<float4*>(out + (size_t)row * NCOL + base);
    __stcs(o4,     r0);
    __stcs(o4 + 1, r1);
}

extern "C" void kernel_launch(void* const* d_in, const int* in_sizes, int n_in,
                              void* d_out, int out_size)
{
    const float* x    = (const float*)d_in[0];
    const float* kern = (const float*)d_in[1];
    float*       out  = (float*)d_out;

    wavelet_fused_kernel<<<4096, NT>>>(x, kern, out);  // one block per row
}